// round 12
// baseline (speedup 1.0000x reference)
#include <cuda_runtime.h>
#include <cuda_fp16.h>
#include <cstdint>

#define NB   8
#define LSEQ 512
#define EDIM 1024
#define NH   16
#define HD   64

// Projected Q/K in fp16 (K pre-scaled by 0.125*log2(e)).
__device__ __half g_Qp[NB * LSEQ * EDIM];
__device__ __half g_Kp[NB * LSEQ * EDIM];

#define EXS 0.1803368801111f   /* 0.125 * log2(e), folded into K projection */

// ---------------- helpers ----------------
static __device__ __forceinline__ uint32_t smem_u32(const void* p) {
    uint32_t a;
    asm("{ .reg .u64 t; cvta.to.shared.u64 t, %1; cvt.u32.u64 %0, t; }"
        : "=r"(a) : "l"(p));
    return a;
}
static __device__ __forceinline__ float fast_lg2(float x) {
    float r; asm("lg2.approx.f32 %0, %1;" : "=f"(r) : "f"(x)); return r;
}
static __device__ __forceinline__ void mma16(float c[4], const uint32_t a[4],
                                             const uint32_t b[2]) {
    asm volatile(
        "mma.sync.aligned.m16n8k16.row.col.f32.f16.f16.f32 "
        "{%0,%1,%2,%3},{%4,%5,%6,%7},{%8,%9},{%0,%1,%2,%3};"
        : "+f"(c[0]), "+f"(c[1]), "+f"(c[2]), "+f"(c[3])
        : "r"(a[0]), "r"(a[1]), "r"(a[2]), "r"(a[3]), "r"(b[0]), "r"(b[1]));
}
static __device__ __forceinline__ void mma16h(uint32_t c[2], const uint32_t a[4],
                                              const uint32_t b[2]) {
    asm volatile(
        "mma.sync.aligned.m16n8k16.row.col.f16.f16.f16.f16 "
        "{%0,%1},{%2,%3,%4,%5},{%6,%7},{%0,%1};"
        : "+r"(c[0]), "+r"(c[1])
        : "r"(a[0]), "r"(a[1]), "r"(a[2]), "r"(a[3]), "r"(b[0]), "r"(b[1]));
}
static __device__ __forceinline__ uint32_t ex2h2(uint32_t x) {
    uint32_t r; asm("ex2.approx.f16x2 %0, %1;" : "=r"(r) : "r"(x)); return r;
}
static __device__ __forceinline__ uint32_t hadd2u(uint32_t a, uint32_t b) {
    uint32_t r; asm("add.rn.f16x2 %0, %1, %2;" : "=r"(r) : "r"(a), "r"(b)); return r;
}
#define LDSM4(r, addr) \
    asm volatile("ldmatrix.sync.aligned.m8n8.x4.shared.b16 {%0,%1,%2,%3},[%4];" \
        : "=r"((r)[0]), "=r"((r)[1]), "=r"((r)[2]), "=r"((r)[3]) : "r"(addr))
#define LDSM2(r, addr) \
    asm volatile("ldmatrix.sync.aligned.m8n8.x2.shared.b16 {%0,%1},[%2];" \
        : "=r"((r)[0]), "=r"((r)[1]) : "r"(addr))
#define CP16(dst, src) \
    asm volatile("cp.async.cg.shared.global [%0], [%1], 16;" :: "r"(dst), "l"(src))
#define CP_COMMIT() asm volatile("cp.async.commit_group;")
#define CP_WAIT(n)  asm volatile("cp.async.wait_group %0;" :: "n"(n))

static __device__ __forceinline__ uint32_t h2bits(float a, float b) {
    __half2 h = __floats2half2_rn(a, b);
    return *reinterpret_cast<uint32_t*>(&h);
}

// ================= fused convert+projection GEMM =================
// C[m,n] = sum_k A[m,k]*W[n,k]; A,W fp32 in gmem, converted to fp16 inline
// during the smem staging (same __floats2half2_rn rounding as the old cvt
// kernel -> bit-identical results). 128m x 128n tile, KC=32, 3-stage smem,
// 1 barrier/kc, 8 warps (2m x 4n). Threads 0-127 load A rows, 128-255 W rows.
// Row stride 80B (16 data u32 + 4 pad) -> conflict-free ldmatrix.
#define PJST   20                      // u32 per 32-half k-row
#define PJ_SLAB (128 * PJST)           // 2560 u32 per matrix slab
#define PJ_SMEM (3 * 2 * PJ_SLAB * 4)  // 3 stages x (A,W) = 60 KB

__global__ void __launch_bounds__(256, 2)
proj_f(const float* __restrict__ Aq, const float* __restrict__ Wq, __half* __restrict__ Cq,
       const float* __restrict__ Am, const float* __restrict__ Wm, __half* __restrict__ Cm) {
    extern __shared__ uint32_t su[];
    const float* A = blockIdx.z ? Am : Aq;
    const float* W = blockIdx.z ? Wm : Wq;
    __half* C      = blockIdx.z ? Cm : Cq;
    const float osc = blockIdx.z ? EXS : 1.0f;   // fold logit scale into K

    const int tid = threadIdx.x, lane = tid & 31, wid = tid >> 5;
    const int wm = wid & 1, wn = wid >> 1, g = lane >> 2, tig = lane & 3;
    const int m0 = blockIdx.y * 128, n0 = blockIdx.x * 128;
    const uint32_t smb = smem_u32(su);

    // loader role: threads 0-127 -> A rows, 128-255 -> W rows
    const int mat  = tid >> 7;           // 0 = A, 1 = W
    const int lrow = tid & 127;
    const float* srcM = mat ? (W + (size_t)n0 * EDIM) : (A + (size_t)m0 * EDIM);
    const float* srow = srcM + (size_t)lrow * EDIM;
    const uint32_t drow = (uint32_t)(mat * PJ_SLAB + lrow * PJST);

    // ldmatrix fragment offsets
    const int l16 = lane & 15;
    uint32_t aoff[4], boff[4];
#pragma unroll
    for (int mt = 0; mt < 4; mt++)
        aoff[mt] = (uint32_t)((wm * 64 + mt * 16 + l16) * PJST + (lane >> 4) * 4) * 4u;
#pragma unroll
    for (int nt = 0; nt < 4; nt++)
        boff[nt] = (uint32_t)(PJ_SLAB + ((wn * 32 + nt * 8 + (l16 & 7)) * PJST
                                         + ((l16 >> 3) & 1) * 4)) * 4u;

    float acc[4][4][4];
#pragma unroll
    for (int i = 0; i < 4; i++)
#pragma unroll
        for (int j = 0; j < 4; j++)
#pragma unroll
            for (int k = 0; k < 4; k++) acc[i][j][k] = 0.f;

    // prologue: fill stages 0 and 1 (LDG -> cvt -> STS)
#pragma unroll
    for (int kc = 0; kc < 2; kc++) {
        const uint32_t dbase = (uint32_t)(kc * 2 * PJ_SLAB) + drow;
        const float4* sp = reinterpret_cast<const float4*>(srow + kc * 32);
#pragma unroll
        for (int c = 0; c < 4; c++) {
            float4 v0 = sp[2 * c], v1 = sp[2 * c + 1];
            uint4 o = make_uint4(h2bits(v0.x, v0.y), h2bits(v0.z, v0.w),
                                 h2bits(v1.x, v1.y), h2bits(v1.z, v1.w));
            *reinterpret_cast<uint4*>(su + dbase + c * 4) = o;
        }
    }

    for (int kc = 0; kc < 32; kc++) {
        const int st = kc % 3;
        __syncthreads();    // stage st ready; stage (kc+2)%3 free for writing

        const bool ld = (kc + 2 < 32);
        const float4* sp = reinterpret_cast<const float4*>(srow + (kc + 2) * 32);
        const uint32_t dbase = (uint32_t)(((kc + 2) % 3) * 2 * PJ_SLAB) + drow;

        // pair {0,1}: issue LDGs, cover latency with k2=0 mma chunk
        float4 p0, p1, p2, p3;
        if (ld) { p0 = sp[0]; p1 = sp[1]; p2 = sp[2]; p3 = sp[3]; }

        const uint32_t aB = smb + (uint32_t)(st * 2 * PJ_SLAB) * 4u;
        {
            uint32_t af[4][4], bf[4][2];
#pragma unroll
            for (int mt = 0; mt < 4; mt++) LDSM4(af[mt], aB + aoff[mt]);
#pragma unroll
            for (int nt = 0; nt < 4; nt++) LDSM2(bf[nt], aB + boff[nt]);
#pragma unroll
            for (int mt = 0; mt < 4; mt++)
#pragma unroll
                for (int nt = 0; nt < 4; nt++)
                    mma16(acc[mt][nt], af[mt], bf[nt]);
        }
        if (ld) {
            uint4 o0 = make_uint4(h2bits(p0.x, p0.y), h2bits(p0.z, p0.w),
                                  h2bits(p1.x, p1.y), h2bits(p1.z, p1.w));
            uint4 o1 = make_uint4(h2bits(p2.x, p2.y), h2bits(p2.z, p2.w),
                                  h2bits(p3.x, p3.y), h2bits(p3.z, p3.w));
            *reinterpret_cast<uint4*>(su + dbase)     = o0;
            *reinterpret_cast<uint4*>(su + dbase + 4) = o1;
            // pair {2,3}: issue LDGs, cover with k2=1 mma chunk
            p0 = sp[4]; p1 = sp[5]; p2 = sp[6]; p3 = sp[7];
        }
        {
            uint32_t af[4][4], bf[4][2];
#pragma unroll
            for (int mt = 0; mt < 4; mt++) LDSM4(af[mt], aB + aoff[mt] + 32u);
#pragma unroll
            for (int nt = 0; nt < 4; nt++) LDSM2(bf[nt], aB + boff[nt] + 32u);
#pragma unroll
            for (int mt = 0; mt < 4; mt++)
#pragma unroll
                for (int nt = 0; nt < 4; nt++)
                    mma16(acc[mt][nt], af[mt], bf[nt]);
        }
        if (ld) {
            uint4 o0 = make_uint4(h2bits(p0.x, p0.y), h2bits(p0.z, p0.w),
                                  h2bits(p1.x, p1.y), h2bits(p1.z, p1.w));
            uint4 o1 = make_uint4(h2bits(p2.x, p2.y), h2bits(p2.z, p2.w),
                                  h2bits(p3.x, p3.y), h2bits(p3.z, p3.w));
            *reinterpret_cast<uint4*>(su + dbase + 8)  = o0;
            *reinterpret_cast<uint4*>(su + dbase + 12) = o1;
        }
    }
    // epilogue: fp32 acc (scaled for K) -> packed half2 stores
    uint32_t* Cu = reinterpret_cast<uint32_t*>(C);
#pragma unroll
    for (int mt = 0; mt < 4; mt++) {
        const int row = m0 + wm * 64 + mt * 16 + g;
#pragma unroll
        for (int nt = 0; nt < 4; nt++) {
            const int colu = (n0 + wn * 32 + nt * 8) / 2 + tig;
            Cu[(size_t)row * (EDIM / 2) + colu] =
                h2bits(acc[mt][nt][0] * osc, acc[mt][nt][1] * osc);
            Cu[(size_t)(row + 8) * (EDIM / 2) + colu] =
                h2bits(acc[mt][nt][2] * osc, acc[mt][nt][3] * osc);
        }
    }
}

// ================= fp16 attention energies (r8/r11 config, barrier-free) =================
// Block (kt64, h, b): 8 warps; warp w owns a=w entirely (512 q rows, 16 iters
// of 32 rows), private double-buffered Q slice -> NO __syncthreads in mainloop.
// K tile (64k x 64d) shared read-only after one initial barrier.
// smem: K 8KB | Q 8 warps x 2 stages x 4KB = 64KB | red 2KB  = 74KB -> 3 blocks/SM
#define AT_K_U32  2048
#define AT_Q_U32  16384
#define AT_SMEM   ((AT_K_U32 + AT_Q_U32 + 512) * 4)

__global__ void __launch_bounds__(256, 3)
attn_h(const __half* __restrict__ Qp, const __half* __restrict__ Kp,
       float* __restrict__ out) {
    extern __shared__ uint32_t su[];
    const int tid = threadIdx.x, lane = tid & 31, wid = tid >> 5;
    const int kt = blockIdx.x, h = blockIdx.y, b = blockIdx.z;
    const uint32_t smb = smem_u32(su);
    float* red = reinterpret_cast<float*>(su + AT_K_U32 + AT_Q_U32);

    // ---- K tile: 64 k-rows x 64 halves, swizzled 128B rows ----
#pragma unroll
    for (int s = 0; s < 2; s++) {
        const int f = tid + 256 * s, row = f >> 3, ch = f & 7;
        const int swz = ch ^ (row & 7);
        CP16(smb + (uint32_t)(row * 32 + swz * 4) * 4u,
             Kp + (size_t)(b * LSEQ + kt * 64 + row) * EDIM + h * HD + ch * 8);
    }
    CP_COMMIT();

    // ---- per-warp private Q slice: 2 stages x 32 rows x 128B ----
    const uint32_t qw = smb + (uint32_t)(AT_K_U32 + wid * 2048) * 4u;
    auto ISSUE = [&](int i) {
        const __half* src = Qp + (size_t)(wid * LSEQ + i * 32) * EDIM + h * HD;
        const uint32_t d0 = qw + (uint32_t)(i & 1) * 4096u;
#pragma unroll
        for (int s = 0; s < 8; s++) {
            const int f = lane + 32 * s, row = f >> 3, ch = f & 7;
            const int swz = ch ^ (row & 7);
            CP16(d0 + (uint32_t)(row * 32 + swz * 4) * 4u,
                 src + (size_t)row * EDIM + ch * 8);
        }
        CP_COMMIT();
    };
    ISSUE(0); ISSUE(1);
    CP_WAIT(2);        // K group retired for this thread
    __syncthreads();   // K visible to all warps (only barrier before epilogue)

    // ldmatrix offsets (swizzle folded: XOR terms touch only chunk bits 4-6)
    const int l7 = lane & 7;
    const uint32_t qa_base = (uint32_t)((l7 + 8 * ((lane >> 3) & 1)) * 128
                                        + (((lane >> 4) ^ l7) * 16));
    const uint32_t ka_base = (uint32_t)(l7 * 128 + (((lane >> 3) ^ l7) * 16));

    uint32_t csum[8];
#pragma unroll
    for (int nt = 0; nt < 8; nt++) csum[nt] = 0u;

    for (int i = 0; i < 16; i++) {
        if (i < 15) { CP_WAIT(1); } else { CP_WAIT(0); }
        const uint32_t qst = qw + (uint32_t)(i & 1) * 4096u;

        uint32_t acc[2][8][2];
#pragma unroll
        for (int mt = 0; mt < 2; mt++)
#pragma unroll
            for (int nt = 0; nt < 8; nt++) { acc[mt][nt][0] = 0u; acc[mt][nt][1] = 0u; }

#pragma unroll
        for (int ksp = 0; ksp < 2; ksp++) {
            uint32_t qf[2][2][4];   // [kk][mt]
#pragma unroll
            for (int kk = 0; kk < 2; kk++)
#pragma unroll
                for (int mt = 0; mt < 2; mt++)
                    LDSM4(qf[kk][mt],
                          qst + (uint32_t)(mt * 2048)
                              + (qa_base ^ ((uint32_t)(2 * ksp + kk) << 5)));
#pragma unroll
            for (int nt = 0; nt < 8; nt++) {
                uint32_t kw[4];     // b-frags for ks=2ksp (kw[0..1]) and 2ksp+1 (kw[2..3])
                LDSM4(kw, smb + (uint32_t)(nt * 1024)
                              + (ka_base ^ ((uint32_t)ksp << 6)));
                mma16h(acc[0][nt], qf[0][0], &kw[0]);
                mma16h(acc[1][nt], qf[0][1], &kw[0]);
                mma16h(acc[0][nt], qf[1][0], &kw[2]);
                mma16h(acc[1][nt], qf[1][1], &kw[2]);
            }
        }
        if (i < 14) ISSUE(i + 2);   // prefetch into just-consumed stage

        // exp2 on packed f16 logits; accumulate per column pair in f16x2
#pragma unroll
        for (int nt = 0; nt < 8; nt++) {
            uint32_t e0 = ex2h2(acc[0][nt][0]);
            uint32_t e1 = ex2h2(acc[0][nt][1]);
            uint32_t e2 = ex2h2(acc[1][nt][0]);
            uint32_t e3 = ex2h2(acc[1][nt][1]);
            csum[nt] = hadd2u(csum[nt], hadd2u(hadd2u(e0, e1), hadd2u(e2, e3)));
        }
    }

    // per-warp: reduce over q-row groups, take log2 of sum (a = wid)
#pragma unroll
    for (int nt = 0; nt < 8; nt++) {
        uint32_t v = csum[nt];
        v = hadd2u(v, __shfl_xor_sync(0xffffffffu, v, 4));
        v = hadd2u(v, __shfl_xor_sync(0xffffffffu, v, 8));
        v = hadd2u(v, __shfl_xor_sync(0xffffffffu, v, 16));
        if (lane < 4) {
            float2 f = __half22float2(*reinterpret_cast<__half2*>(&v));
            float2 lg = make_float2(fast_lg2(f.x), fast_lg2(f.y));
            *reinterpret_cast<float2*>(&red[wid * 64 + nt * 8 + lane * 2]) = lg;
        }
    }
    __syncthreads();
    if (tid < 64) {
        float s = 0.f;
#pragma unroll
        for (int w = 0; w < 8; w++) s += red[w * 64 + tid];
        out[((size_t)(b * NH + h)) * LSEQ + kt * 64 + tid] = 0.69314718056f * s;
    }
}

// ================= host =================
extern "C" void kernel_launch(void* const* d_in, const int* in_sizes, int n_in,
                              void* d_out, int out_size) {
    (void)in_sizes; (void)n_in; (void)out_size;
    const float* query  = (const float*)d_in[0];
    const float* memory = (const float*)d_in[1];
    const float* W_Q    = (const float*)d_in[2];
    const float* W_K    = (const float*)d_in[3];
    float* out = (float*)d_out;

    __half *qp, *kp;
    cudaGetSymbolAddress((void**)&qp, g_Qp);
    cudaGetSymbolAddress((void**)&kp, g_Kp);

    cudaFuncSetAttribute(proj_f, cudaFuncAttributeMaxDynamicSharedMemorySize, PJ_SMEM);
    cudaFuncSetAttribute(attn_h, cudaFuncAttributeMaxDynamicSharedMemorySize, AT_SMEM);

    dim3 gP(EDIM / 128, (NB * LSEQ) / 128, 2);   // 8 x 32 x 2 = 512 blocks
    proj_f<<<gP, 256, PJ_SMEM>>>(query, W_Q, qp, memory, W_K, kp);

    dim3 gA(LSEQ / 64, NH, NB);                  // 8 x 16 x 8 = 1024 blocks
    attn_h<<<gA, 256, AT_SMEM>>>(qp, kp, out);
}

// round 13
// speedup vs baseline: 1.6554x; 1.6554x over previous
#include <cuda_runtime.h>
#include <cuda_fp16.h>
#include <cstdint>

#define NB   8
#define LSEQ 512
#define EDIM 1024
#define NH   16
#define HD   64

// fp16 staging for inputs/weights and projected Q/K.
__device__ __half g_qh[NB * LSEQ * EDIM];
__device__ __half g_mh[NB * LSEQ * EDIM];
__device__ __half g_wqh[EDIM * EDIM];
__device__ __half g_wkh[EDIM * EDIM];
__device__ __half g_Qp[NB * LSEQ * EDIM];
__device__ __half g_Kp[NB * LSEQ * EDIM];   // pre-scaled by 0.125*log2(e)

#define EXS 0.1803368801111f   /* 0.125 * log2(e), folded into K projection */

// ---------------- helpers ----------------
static __device__ __forceinline__ uint32_t smem_u32(const void* p) {
    uint32_t a;
    asm("{ .reg .u64 t; cvta.to.shared.u64 t, %1; cvt.u32.u64 %0, t; }"
        : "=r"(a) : "l"(p));
    return a;
}
static __device__ __forceinline__ float fast_lg2(float x) {
    float r; asm("lg2.approx.f32 %0, %1;" : "=f"(r) : "f"(x)); return r;
}
// f16-accumulate mma: D packs adjacent columns per u32
static __device__ __forceinline__ void mma16h(uint32_t c[2], const uint32_t a[4],
                                              const uint32_t b[2]) {
    asm volatile(
        "mma.sync.aligned.m16n8k16.row.col.f16.f16.f16.f16 "
        "{%0,%1},{%2,%3,%4,%5},{%6,%7},{%0,%1};"
        : "+r"(c[0]), "+r"(c[1])
        : "r"(a[0]), "r"(a[1]), "r"(a[2]), "r"(a[3]), "r"(b[0]), "r"(b[1]));
}
static __device__ __forceinline__ uint32_t ex2h2(uint32_t x) {
    uint32_t r; asm("ex2.approx.f16x2 %0, %1;" : "=r"(r) : "r"(x)); return r;
}
static __device__ __forceinline__ uint32_t hadd2u(uint32_t a, uint32_t b) {
    uint32_t r; asm("add.rn.f16x2 %0, %1, %2;" : "=r"(r) : "r"(a), "r"(b)); return r;
}
static __device__ __forceinline__ float2 h22f2(uint32_t u) {
    return __half22float2(*reinterpret_cast<__half2*>(&u));
}
#define LDSM4(r, addr) \
    asm volatile("ldmatrix.sync.aligned.m8n8.x4.shared.b16 {%0,%1,%2,%3},[%4];" \
        : "=r"((r)[0]), "=r"((r)[1]), "=r"((r)[2]), "=r"((r)[3]) : "r"(addr))
#define LDSM2(r, addr) \
    asm volatile("ldmatrix.sync.aligned.m8n8.x2.shared.b16 {%0,%1},[%2];" \
        : "=r"((r)[0]), "=r"((r)[1]) : "r"(addr))
#define CP16(dst, src) \
    asm volatile("cp.async.cg.shared.global [%0], [%1], 16;" :: "r"(dst), "l"(src))
#define CP_COMMIT() asm volatile("cp.async.commit_group;")
#define CP_WAIT(n)  asm volatile("cp.async.wait_group %0;" :: "n"(n))

static __device__ __forceinline__ uint32_t h2bits(float a, float b) {
    __half2 h = __floats2half2_rn(a, b);
    return *reinterpret_cast<uint32_t*>(&h);
}

// ================= fused fp32 -> fp16 conversion (single launch) =================
#define NIN4 (NB * LSEQ * EDIM / 4)
#define NW4  (EDIM * EDIM / 4)

__global__ void __launch_bounds__(256)
cvt_all(const float4* __restrict__ q,  const float4* __restrict__ m,
        const float4* __restrict__ wq, const float4* __restrict__ wk,
        uint2* __restrict__ dq,  uint2* __restrict__ dm,
        uint2* __restrict__ dwq, uint2* __restrict__ dwk) {
    const int total = 2 * NIN4 + 2 * NW4;
    int i = blockIdx.x * blockDim.x + threadIdx.x;
    const int stride = gridDim.x * blockDim.x;
    for (; i < total; i += stride) {
        const float4* s; uint2* d; int j;
        if (i < NIN4)            { s = q;  d = dq;  j = i; }
        else if (i < 2 * NIN4)   { s = m;  d = dm;  j = i - NIN4; }
        else if (i < 2 * NIN4 + NW4) { s = wq; d = dwq; j = i - 2 * NIN4; }
        else                     { s = wk; d = dwk; j = i - 2 * NIN4 - NW4; }
        float4 v = s[j];
        d[j] = make_uint2(h2bits(v.x, v.y), h2bits(v.z, v.w));
    }
}

// ================= fp16 projection GEMM (f16-acc, register split-K) =================
// C[m,n] = sum_k A[m,k]*W[n,k]; 128m x 128n tile, KC=32, 4-stage cp.async
// (3 in flight, 1 barrier/kc -> 32 barriers), 8 warps (2m x 4n).
// f16-D mma at 2x tensor rate; two f16 acc sets alternated by kc parity
// (each K-depth 512), folded in f32 at the epilogue.
#define PJST   20                  // u32 per 32-half k-row
#define PJ_SLAB (128 * PJST)       // 2560 u32 per slab stage
#define PJ_SMEM (8 * PJ_SLAB * 4)  // 4 A-stages + 4 W-stages = 80 KB

__global__ void __launch_bounds__(256, 2)
proj_h(const __half* __restrict__ Aq, const __half* __restrict__ Wq, __half* __restrict__ Cq,
       const __half* __restrict__ Am, const __half* __restrict__ Wm, __half* __restrict__ Cm) {
    extern __shared__ uint32_t su[];
    const __half* A = blockIdx.z ? Am : Aq;
    const __half* W = blockIdx.z ? Wm : Wq;
    __half* C       = blockIdx.z ? Cm : Cq;
    const float osc = blockIdx.z ? EXS : 1.0f;   // fold logit scale into K

    const int tid = threadIdx.x, lane = tid & 31, wid = tid >> 5;
    const int wm = wid & 1, wn = wid >> 1, g = lane >> 2, tig = lane & 3;
    const int m0 = blockIdx.y * 128, n0 = blockIdx.x * 128;
    const uint32_t smb = smem_u32(su);

    const int l16 = lane & 15;
    uint32_t aoff[4], boff[4];
#pragma unroll
    for (int mt = 0; mt < 4; mt++)
        aoff[mt] = (uint32_t)((wm * 64 + mt * 16 + l16) * PJST + (lane >> 4) * 4) * 4u;
#pragma unroll
    for (int nt = 0; nt < 4; nt++)
        boff[nt] = (uint32_t)((wn * 32 + nt * 8 + (l16 & 7)) * PJST + ((l16 >> 3) & 1) * 4) * 4u;

    // two f16 accumulator sets (split-K by kc parity)
    uint32_t acc[2][4][4][2];
#pragma unroll
    for (int s = 0; s < 2; s++)
#pragma unroll
        for (int i = 0; i < 4; i++)
#pragma unroll
            for (int j = 0; j < 4; j++) { acc[s][i][j][0] = 0u; acc[s][i][j][1] = 0u; }

    // cp.async: 2 CP16/thread per slab (A,W): 128 rows x 4 x 16B chunks
    const int crow = tid >> 2, cch = tid & 3;
    auto ISSUE = [&](int kc) {
        const int st = kc & 3;
#pragma unroll
        for (int s = 0; s < 2; s++) {
            const int row = crow + 64 * s;
            CP16(smb + (uint32_t)(st * PJ_SLAB + row * PJST + cch * 4) * 4u,
                 A + (size_t)(m0 + row) * EDIM + kc * 32 + cch * 8);
            CP16(smb + (uint32_t)((4 + st) * PJ_SLAB + row * PJST + cch * 4) * 4u,
                 W + (size_t)(n0 + row) * EDIM + kc * 32 + cch * 8);
        }
        CP_COMMIT();
    };
    ISSUE(0); ISSUE(1); ISSUE(2);

    for (int kc = 0; kc < 32; kc++) {
        const int st = kc & 3, ps = kc & 1;
        CP_WAIT(2);
        __syncthreads();
        if (kc + 3 < 32) ISSUE(kc + 3);
        const uint32_t aB = smb + (uint32_t)(st * PJ_SLAB) * 4u;
        const uint32_t bB = smb + (uint32_t)((4 + st) * PJ_SLAB) * 4u;
#pragma unroll
        for (int k2 = 0; k2 < 2; k2++) {   // two 16-k chunks per stage
            uint32_t af[4][4], bf[4][2];
#pragma unroll
            for (int mt = 0; mt < 4; mt++)
                LDSM4(af[mt], aB + aoff[mt] + (uint32_t)(k2 * 32));
#pragma unroll
            for (int nt = 0; nt < 4; nt++)
                LDSM2(bf[nt], bB + boff[nt] + (uint32_t)(k2 * 32));
#pragma unroll
            for (int mt = 0; mt < 4; mt++)
#pragma unroll
                for (int nt = 0; nt < 4; nt++)
                    mma16h(acc[ps][mt][nt], af[mt], bf[nt]);
        }
    }
    // epilogue: fold the two f16 sets in f32, scale, pack, store
    uint32_t* Cu = reinterpret_cast<uint32_t*>(C);
#pragma unroll
    for (int mt = 0; mt < 4; mt++) {
        const int row = m0 + wm * 64 + mt * 16 + g;
#pragma unroll
        for (int nt = 0; nt < 4; nt++) {
            const int colu = (n0 + wn * 32 + nt * 8) / 2 + tig;
            float2 f0a = h22f2(acc[0][mt][nt][0]), f0b = h22f2(acc[1][mt][nt][0]);
            float2 f1a = h22f2(acc[0][mt][nt][1]), f1b = h22f2(acc[1][mt][nt][1]);
            Cu[(size_t)row * (EDIM / 2) + colu] =
                h2bits((f0a.x + f0b.x) * osc, (f0a.y + f0b.y) * osc);
            Cu[(size_t)(row + 8) * (EDIM / 2) + colu] =
                h2bits((f1a.x + f1b.x) * osc, (f1a.y + f1b.y) * osc);
        }
    }
}

// ================= fp16 attention energies (r8/r11 config, barrier-free) =================
// Block (kt64, h, b): 8 warps; warp w owns a=w entirely (512 q rows, 16 iters
// of 32 rows), private double-buffered Q slice -> NO __syncthreads in mainloop.
// K tile (64k x 64d) shared read-only after one initial barrier.
// smem: K 8KB | Q 8 warps x 2 stages x 4KB = 64KB | red 2KB  = 74KB -> 3 blocks/SM
#define AT_K_U32  2048
#define AT_Q_U32  16384
#define AT_SMEM   ((AT_K_U32 + AT_Q_U32 + 512) * 4)

__global__ void __launch_bounds__(256, 3)
attn_h(const __half* __restrict__ Qp, const __half* __restrict__ Kp,
       float* __restrict__ out) {
    extern __shared__ uint32_t su[];
    const int tid = threadIdx.x, lane = tid & 31, wid = tid >> 5;
    const int kt = blockIdx.x, h = blockIdx.y, b = blockIdx.z;
    const uint32_t smb = smem_u32(su);
    float* red = reinterpret_cast<float*>(su + AT_K_U32 + AT_Q_U32);

    // ---- K tile: 64 k-rows x 64 halves, swizzled 128B rows ----
#pragma unroll
    for (int s = 0; s < 2; s++) {
        const int f = tid + 256 * s, row = f >> 3, ch = f & 7;
        const int swz = ch ^ (row & 7);
        CP16(smb + (uint32_t)(row * 32 + swz * 4) * 4u,
             Kp + (size_t)(b * LSEQ + kt * 64 + row) * EDIM + h * HD + ch * 8);
    }
    CP_COMMIT();

    // ---- per-warp private Q slice: 2 stages x 32 rows x 128B ----
    const uint32_t qw = smb + (uint32_t)(AT_K_U32 + wid * 2048) * 4u;
    auto ISSUE = [&](int i) {
        const __half* src = Qp + (size_t)(wid * LSEQ + i * 32) * EDIM + h * HD;
        const uint32_t d0 = qw + (uint32_t)(i & 1) * 4096u;
#pragma unroll
        for (int s = 0; s < 8; s++) {
            const int f = lane + 32 * s, row = f >> 3, ch = f & 7;
            const int swz = ch ^ (row & 7);
            CP16(d0 + (uint32_t)(row * 32 + swz * 4) * 4u,
                 src + (size_t)row * EDIM + ch * 8);
        }
        CP_COMMIT();
    };
    ISSUE(0); ISSUE(1);
    CP_WAIT(2);        // K group retired for this thread
    __syncthreads();   // K visible to all warps (only barrier before epilogue)

    // ldmatrix offsets (swizzle folded: XOR terms touch only chunk bits 4-6)
    const int l7 = lane & 7;
    const uint32_t qa_base = (uint32_t)((l7 + 8 * ((lane >> 3) & 1)) * 128
                                        + (((lane >> 4) ^ l7) * 16));
    const uint32_t ka_base = (uint32_t)(l7 * 128 + (((lane >> 3) ^ l7) * 16));

    uint32_t csum[8];
#pragma unroll
    for (int nt = 0; nt < 8; nt++) csum[nt] = 0u;

    for (int i = 0; i < 16; i++) {
        if (i < 15) { CP_WAIT(1); } else { CP_WAIT(0); }
        const uint32_t qst = qw + (uint32_t)(i & 1) * 4096u;

        uint32_t acc[2][8][2];
#pragma unroll
        for (int mt = 0; mt < 2; mt++)
#pragma unroll
            for (int nt = 0; nt < 8; nt++) { acc[mt][nt][0] = 0u; acc[mt][nt][1] = 0u; }

#pragma unroll
        for (int ksp = 0; ksp < 2; ksp++) {
            uint32_t qf[2][2][4];   // [kk][mt]
#pragma unroll
            for (int kk = 0; kk < 2; kk++)
#pragma unroll
                for (int mt = 0; mt < 2; mt++)
                    LDSM4(qf[kk][mt],
                          qst + (uint32_t)(mt * 2048)
                              + (qa_base ^ ((uint32_t)(2 * ksp + kk) << 5)));
#pragma unroll
            for (int nt = 0; nt < 8; nt++) {
                uint32_t kw[4];     // b-frags for ks=2ksp (kw[0..1]) and 2ksp+1 (kw[2..3])
                LDSM4(kw, smb + (uint32_t)(nt * 1024)
                              + (ka_base ^ ((uint32_t)ksp << 6)));
                mma16h(acc[0][nt], qf[0][0], &kw[0]);
                mma16h(acc[1][nt], qf[0][1], &kw[0]);
                mma16h(acc[0][nt], qf[1][0], &kw[2]);
                mma16h(acc[1][nt], qf[1][1], &kw[2]);
            }
        }
        if (i < 14) ISSUE(i + 2);   // prefetch into just-consumed stage

        // exp2 on packed f16 logits; accumulate per column pair in f16x2
#pragma unroll
        for (int nt = 0; nt < 8; nt++) {
            uint32_t e0 = ex2h2(acc[0][nt][0]);
            uint32_t e1 = ex2h2(acc[0][nt][1]);
            uint32_t e2 = ex2h2(acc[1][nt][0]);
            uint32_t e3 = ex2h2(acc[1][nt][1]);
            csum[nt] = hadd2u(csum[nt], hadd2u(hadd2u(e0, e1), hadd2u(e2, e3)));
        }
    }

    // per-warp: reduce over q-row groups, take log2 of sum (a = wid)
#pragma unroll
    for (int nt = 0; nt < 8; nt++) {
        uint32_t v = csum[nt];
        v = hadd2u(v, __shfl_xor_sync(0xffffffffu, v, 4));
        v = hadd2u(v, __shfl_xor_sync(0xffffffffu, v, 8));
        v = hadd2u(v, __shfl_xor_sync(0xffffffffu, v, 16));
        if (lane < 4) {
            float2 f = h22f2(v);
            float2 lg = make_float2(fast_lg2(f.x), fast_lg2(f.y));
            *reinterpret_cast<float2*>(&red[wid * 64 + nt * 8 + lane * 2]) = lg;
        }
    }
    __syncthreads();
    if (tid < 64) {
        float s = 0.f;
#pragma unroll
        for (int w = 0; w < 8; w++) s += red[w * 64 + tid];
        out[((size_t)(b * NH + h)) * LSEQ + kt * 64 + tid] = 0.69314718056f * s;
    }
}

// ================= host =================
extern "C" void kernel_launch(void* const* d_in, const int* in_sizes, int n_in,
                              void* d_out, int out_size) {
    (void)in_sizes; (void)n_in; (void)out_size;
    const float* query  = (const float*)d_in[0];
    const float* memory = (const float*)d_in[1];
    const float* W_Q    = (const float*)d_in[2];
    const float* W_K    = (const float*)d_in[3];
    float* out = (float*)d_out;

    __half *qh, *mh, *wqh, *wkh, *qp, *kp;
    cudaGetSymbolAddress((void**)&qh,  g_qh);
    cudaGetSymbolAddress((void**)&mh,  g_mh);
    cudaGetSymbolAddress((void**)&wqh, g_wqh);
    cudaGetSymbolAddress((void**)&wkh, g_wkh);
    cudaGetSymbolAddress((void**)&qp,  g_Qp);
    cudaGetSymbolAddress((void**)&kp,  g_Kp);

    cudaFuncSetAttribute(proj_h, cudaFuncAttributeMaxDynamicSharedMemorySize, PJ_SMEM);
    cudaFuncSetAttribute(attn_h, cudaFuncAttributeMaxDynamicSharedMemorySize, AT_SMEM);

    cvt_all<<<2368, 256>>>((const float4*)query, (const float4*)memory,
                           (const float4*)W_Q,   (const float4*)W_K,
                           (uint2*)qh, (uint2*)mh, (uint2*)wqh, (uint2*)wkh);

    dim3 gP(EDIM / 128, (NB * LSEQ) / 128, 2);   // 8 x 32 x 2 = 512 blocks
    proj_h<<<gP, 256, PJ_SMEM>>>(qh, wqh, qp, mh, wkh, kp);

    dim3 gA(LSEQ / 64, NH, NB);                  // 8 x 16 x 8 = 1024 blocks
    attn_h<<<gA, 256, AT_SMEM>>>(qp, kp, out);
}